// round 16
// baseline (speedup 1.0000x reference)
#include <cuda_runtime.h>
#include <cuda_bf16.h>
#include <cstdint>

// CRF negative log-likelihood, fixed shapes. sm_100a.
// Warp-autonomous recurrence: 1 warp per sequence, 2 tags/thread (bf16x2),
// no block barrier (syncwarp only), renorm scale via register shfl.
#define B_ 256
#define S_ 1024
#define T_ 64
#define PF 8   // emission prefetch ring depth; renorm every 4 steps

__device__ float g_diff[B_];

__device__ __forceinline__ uint32_t bfpack(float lo, float hi) {
    uint32_t r;
    asm("cvt.rn.bf16x2.f32 %0, %1, %2;" : "=r"(r) : "f"(hi), "f"(lo));
    return r;
}
__device__ __forceinline__ __nv_bfloat162 asbf2(uint32_t w) {
    return *reinterpret_cast<const __nv_bfloat162*>(&w);
}

// 64 threads = 2 warps = 2 sequences per block; grid = 128 (one clean wave).
// Warp w handles seq b = 2*blk + w; lane l owns output tags 2l, 2l+1.
__global__ void __launch_bounds__(64) crf_forward_kernel(
    const float* __restrict__ emissions,   // (B, S, T)
    const int* __restrict__ tags,          // (B, S) int32
    const float* __restrict__ trans,       // (T, T)
    const float* __restrict__ startT,      // (T,)
    const float* __restrict__ endT)        // (T,)
{
    const int tid = threadIdx.x;
    const int w   = tid >> 5;
    const int l   = tid & 31;
    const int b   = 2 * blockIdx.x + w;
    const int c0  = 2 * l;

    // Per-warp double-buffered u: 64 bf16 = 32 words; lane l writes word l.
    __shared__ __align__(16) uint32_t usm[2][2][32];   // [buf][warp][word]

    // E = exp(trans), packed per input-row-pair for the thread's 2 columns.
    // e0[p] = (E[2p][c0],   E[2p+1][c0]);  e1[p] = same for c0+1.
    __nv_bfloat162 e0[32], e1[32];
#pragma unroll
    for (int p = 0; p < 32; ++p) {
        float a = __expf(__ldg(trans + (2 * p + 0) * T_ + c0));
        float bq = __expf(__ldg(trans + (2 * p + 1) * T_ + c0));
        uint32_t pk = bfpack(a, bq);
        e0[p] = asbf2(pk);
        float a1 = __expf(__ldg(trans + (2 * p + 0) * T_ + c0 + 1));
        float b1 = __expf(__ldg(trans + (2 * p + 1) * T_ + c0 + 1));
        uint32_t pk1 = bfpack(a1, b1);
        e1[p] = asbf2(pk1);
    }

    const float* emb = emissions + (size_t)b * S_ * T_ + c0;  // float2-aligned

    // t = 0: v = exp(start + em0) for the two columns.
    float2 em0 = __ldg((const float2*)emb);
    float v0 = __expf(__ldg(startT + c0)     + em0.x);
    float v1 = __expf(__ldg(startT + c0 + 1) + em0.y);
    usm[0][w][l] = bfpack(v0, v1);
    float cacc = 0.f;   // running log-scale (identical on all lanes)

    // Prefetch ring: raw emission pairs for t = 1..PF.
    float2 pf[PF];
#pragma unroll
    for (int k = 0; k < PF; ++k)
        pf[k] = __ldg((const float2*)(emb + (size_t)(1 + k) * T_));

    __syncwarp();

    int cur = 0;
    int t = 1;

    // Main loop: 127 chunks of 8 steps (t = 1..1016).
#pragma unroll 1
    for (int tb = 0; tb < 127; ++tb) {
#pragma unroll
        for (int k = 0; k < 8; ++k, ++t) {
            float2 em2 = pf[k];
            if (t + PF < S_)
                pf[k] = __ldg((const float2*)(emb + (size_t)(t + PF) * T_));

            float f0 = __expf(em2.x);
            float f1 = __expf(em2.y);
            if ((k & 3) == 0) {                        // compile-time under unroll
                float s = __shfl_sync(0xffffffffu, v0, 0);  // u_prev[0] from register
                cacc += __logf(s);
                float rs = __frcp_rn(s);
                f0 *= rs; f1 *= rs;
            }

            // Dot for both columns: 64 HFMA2, 8 chains of depth 8.
            const uint4* u4 = reinterpret_cast<const uint4*>(usm[cur][w]);
            __nv_bfloat162 z = __floats2bfloat162_rn(0.f, 0.f);
            __nv_bfloat162 A0 = z, A1 = z, A2 = z, A3 = z;
            __nv_bfloat162 B0 = z, B1 = z, B2 = z, B3 = z;
#pragma unroll
            for (int i = 0; i < 8; ++i) {
                uint4 q = u4[i];
                __nv_bfloat162 qx = asbf2(q.x), qy = asbf2(q.y);
                __nv_bfloat162 qz = asbf2(q.z), qw = asbf2(q.w);
                A0 = __hfma2(qx, e0[4 * i + 0], A0);
                B0 = __hfma2(qx, e1[4 * i + 0], B0);
                A1 = __hfma2(qy, e0[4 * i + 1], A1);
                B1 = __hfma2(qy, e1[4 * i + 1], B1);
                A2 = __hfma2(qz, e0[4 * i + 2], A2);
                B2 = __hfma2(qz, e1[4 * i + 2], B2);
                A3 = __hfma2(qw, e0[4 * i + 3], A3);
                B3 = __hfma2(qw, e1[4 * i + 3], B3);
            }
            A0 = __hadd2(A0, A1); A2 = __hadd2(A2, A3); A0 = __hadd2(A0, A2);
            B0 = __hadd2(B0, B1); B2 = __hadd2(B2, B3); B0 = __hadd2(B0, B2);
            float2 fa = __bfloat1622float2(A0);
            float2 fb = __bfloat1622float2(B0);
            v0 = (fa.x + fa.y) * f0;
            v1 = (fb.x + fb.y) * f1;

            cur ^= 1;
            usm[cur][w][l] = bfpack(v0, v1);
            __syncwarp();
        }
    }
    // Remainder: t = 1017..1023 (7 steps), emissions already in pf[0..6].
#pragma unroll
    for (int k = 0; k < 7; ++k, ++t) {
        float2 em2 = pf[k];

        float f0 = __expf(em2.x);
        float f1 = __expf(em2.y);
        if ((k & 3) == 0) {
            float s = __shfl_sync(0xffffffffu, v0, 0);
            cacc += __logf(s);
            float rs = __frcp_rn(s);
            f0 *= rs; f1 *= rs;
        }

        const uint4* u4 = reinterpret_cast<const uint4*>(usm[cur][w]);
        __nv_bfloat162 z = __floats2bfloat162_rn(0.f, 0.f);
        __nv_bfloat162 A0 = z, A1 = z, A2 = z, A3 = z;
        __nv_bfloat162 B0 = z, B1 = z, B2 = z, B3 = z;
#pragma unroll
        for (int i = 0; i < 8; ++i) {
            uint4 q = u4[i];
            __nv_bfloat162 qx = asbf2(q.x), qy = asbf2(q.y);
            __nv_bfloat162 qz = asbf2(q.z), qw = asbf2(q.w);
            A0 = __hfma2(qx, e0[4 * i + 0], A0);
            B0 = __hfma2(qx, e1[4 * i + 0], B0);
            A1 = __hfma2(qy, e0[4 * i + 1], A1);
            B1 = __hfma2(qy, e1[4 * i + 1], B1);
            A2 = __hfma2(qz, e0[4 * i + 2], A2);
            B2 = __hfma2(qz, e1[4 * i + 2], B2);
            A3 = __hfma2(qw, e0[4 * i + 3], A3);
            B3 = __hfma2(qw, e1[4 * i + 3], B3);
        }
        A0 = __hadd2(A0, A1); A2 = __hadd2(A2, A3); A0 = __hadd2(A0, A2);
        B0 = __hadd2(B0, B1); B2 = __hadd2(B2, B3); B0 = __hadd2(B0, B2);
        float2 fa = __bfloat1622float2(A0);
        float2 fb = __bfloat1622float2(B0);
        v0 = (fa.x + fa.y) * f0;
        v1 = (fb.x + fb.y) * f1;

        cur ^= 1;
        usm[cur][w][l] = bfpack(v0, v1);
        __syncwarp();
    }

    // partition = cacc + log(sum_c v_c * exp(end_c)) — warp shfl reduction.
    float pA = v0 * __expf(__ldg(endT + c0)) + v1 * __expf(__ldg(endT + c0 + 1));
#pragma unroll
    for (int off = 16; off > 0; off >>= 1)
        pA += __shfl_xor_sync(0xffffffffu, pA, off);

    // Gold-path score: this warp's 32 threads stride over time steps.
    float sc = 0.f;
    const int* tg = tags + (size_t)b * S_;
    const float* emS = emissions + (size_t)b * S_ * T_;
#pragma unroll 2
    for (int tt = l; tt < S_; tt += 32) {
        int t0 = tg[tt];
        sc += __ldg(emS + (size_t)tt * T_ + t0);
        if (tt + 1 < S_) sc += __ldg(trans + t0 * T_ + tg[tt + 1]);
    }
#pragma unroll
    for (int off = 16; off > 0; off >>= 1)
        sc += __shfl_xor_sync(0xffffffffu, sc, off);

    if (l == 0) {
        sc += __ldg(startT + tg[0]) + __ldg(endT + tg[S_ - 1]);
        double partition = (double)cacc + (double)__logf(pA);
        g_diff[b] = (float)(partition - (double)sc);
    }
}

__global__ void crf_reduce_kernel(float* __restrict__ out)
{
    __shared__ float sh[B_];
    int t = threadIdx.x;
    sh[t] = g_diff[t];
    __syncthreads();
#pragma unroll
    for (int off = B_ / 2; off > 0; off >>= 1) {
        if (t < off) sh[t] += sh[t + off];
        __syncthreads();
    }
    if (t == 0) out[0] = sh[0] / (float)B_;
}

extern "C" void kernel_launch(void* const* d_in, const int* in_sizes, int n_in,
                              void* d_out, int out_size)
{
    const float* emissions = (const float*)d_in[0];
    const int*   tags      = (const int*)d_in[1];
    const float* trans     = (const float*)d_in[2];
    const float* startT    = (const float*)d_in[3];
    const float* endT      = (const float*)d_in[4];
    float* out = (float*)d_out;

    crf_forward_kernel<<<B_ / 2, 64>>>(emissions, tags, trans, startT, endT);
    crf_reduce_kernel<<<1, B_>>>(out);
}

// round 17
// speedup vs baseline: 1.0169x; 1.0169x over previous
#include <cuda_runtime.h>
#include <cuda_bf16.h>
#include <cstdint>

// CRF negative log-likelihood, fixed shapes. sm_100a.
// Champion R15 body (141.8us): bf16 state + HFMA2 packed dot, 2 seqs/block.
// Launch padded to 5 kernels/call so ncu (-s 5 -c 1) captures the FORWARD kernel.
#define B_ 256
#define S_ 1024
#define T_ 64
#define PF 8   // emission prefetch ring depth; renorm every 4 steps

__device__ float g_diff[B_];

__global__ void crf_noop_kernel() {}

// 128 threads: bat = tid>>6 (2 sequences/block), j = tid&63 (tag).
// grid = 128 (one clean wave).
__global__ void __launch_bounds__(128) crf_forward_kernel(
    const float* __restrict__ emissions,   // (B, S, T)
    const int* __restrict__ tags,          // (B, S) int32
    const float* __restrict__ trans,       // (T, T)
    const float* __restrict__ startT,      // (T,)
    const float* __restrict__ endT)        // (T,)
{
    const int tid = threadIdx.x;
    const int bat = tid >> 6;
    const int j   = tid & 63;
    const int b   = 2 * blockIdx.x + bat;

    __shared__ __align__(16) __nv_bfloat16 u[2][2][T_];   // [buf][bat][tag]
    __shared__ float redA[2][T_];
    __shared__ float redB[2][T_];

    // Packed column of E = exp(trans): epack[m] = (E[2m][j], E[2m+1][j]).
    __nv_bfloat162 epack[T_ / 2];
#pragma unroll
    for (int m = 0; m < T_ / 2; ++m) {
        float lo = __expf(__ldg(trans + (2 * m + 0) * T_ + j));
        float hi = __expf(__ldg(trans + (2 * m + 1) * T_ + j));
        epack[m] = __floats2bfloat162_rn(lo, hi);
    }

    const float* emb = emissions + (size_t)b * S_ * T_ + j;

    // t = 0: u0_j = exp(start_j + em0_j)
    float v = __expf(__ldg(startT + j) + __ldg(emb));
    u[0][bat][j] = __float2bfloat16(v);
    double c = 0.0;   // running log-scale (thread j==0 of each sequence only)

    // Prefetch ring for emissions (raw values, t = 1..PF).
    float pf[PF];
#pragma unroll
    for (int k = 0; k < PF; ++k)
        pf[k] = __ldg(emb + (size_t)(1 + k) * T_);

    __syncthreads();

    int cur = 0;
    int t = 1;

    // Main loop: 127 chunks of 8 steps (t = 1..1016).
#pragma unroll 1
    for (int tb = 0; tb < 127; ++tb) {
#pragma unroll
        for (int k = 0; k < 8; ++k, ++t) {
            float em_t = pf[k];
            if (t + PF < S_)
                pf[k] = __ldg(emb + (size_t)(t + PF) * T_);

            float scale_mul = __expf(em_t);
            if ((k & 3) == 0) {                       // compile-time under unroll
                float scale = __bfloat162float(u[cur][bat][0]);  // broadcast LDS
                if (j == 0) c += (double)__logf(scale);
                scale_mul *= __frcp_rn(scale);
            }

            // 64-MAC dot as 32 HFMA2.BF16: 4 chains (depth 8), 8 LDS.128.
            __nv_bfloat162 z = __floats2bfloat162_rn(0.f, 0.f);
            __nv_bfloat162 a0 = z, a1 = z, a2 = z, a3 = z;
            const uint4* u4 = reinterpret_cast<const uint4*>(u[cur][bat]);
#pragma unroll
            for (int i = 0; i < 8; ++i) {
                uint4 q = u4[i];
                a0 = __hfma2(*(const __nv_bfloat162*)&q.x, epack[4 * i + 0], a0);
                a1 = __hfma2(*(const __nv_bfloat162*)&q.y, epack[4 * i + 1], a1);
                a2 = __hfma2(*(const __nv_bfloat162*)&q.z, epack[4 * i + 2], a2);
                a3 = __hfma2(*(const __nv_bfloat162*)&q.w, epack[4 * i + 3], a3);
            }
            a0 = __hadd2(a0, a1);
            a2 = __hadd2(a2, a3);
            a0 = __hadd2(a0, a2);
            float2 f = __bfloat1622float2(a0);
            v = (f.x + f.y) * scale_mul;

            cur ^= 1;
            u[cur][bat][j] = __float2bfloat16(v);
            __syncthreads();
        }
    }
    // Remainder: t = 1017..1023 (7 steps), emissions already in pf[0..6].
#pragma unroll
    for (int k = 0; k < 7; ++k, ++t) {
        float em_t = pf[k];

        float scale_mul = __expf(em_t);
        if ((k & 3) == 0) {
            float scale = __bfloat162float(u[cur][bat][0]);
            if (j == 0) c += (double)__logf(scale);
            scale_mul *= __frcp_rn(scale);
        }

        __nv_bfloat162 z = __floats2bfloat162_rn(0.f, 0.f);
        __nv_bfloat162 a0 = z, a1 = z, a2 = z, a3 = z;
        const uint4* u4 = reinterpret_cast<const uint4*>(u[cur][bat]);
#pragma unroll
        for (int i = 0; i < 8; ++i) {
            uint4 q = u4[i];
            a0 = __hfma2(*(const __nv_bfloat162*)&q.x, epack[4 * i + 0], a0);
            a1 = __hfma2(*(const __nv_bfloat162*)&q.y, epack[4 * i + 1], a1);
            a2 = __hfma2(*(const __nv_bfloat162*)&q.z, epack[4 * i + 2], a2);
            a3 = __hfma2(*(const __nv_bfloat162*)&q.w, epack[4 * i + 3], a3);
        }
        a0 = __hadd2(a0, a1);
        a2 = __hadd2(a2, a3);
        a0 = __hadd2(a0, a2);
        float2 f = __bfloat1622float2(a0);
        v = (f.x + f.y) * scale_mul;

        cur ^= 1;
        u[cur][bat][j] = __float2bfloat16(v);
        __syncthreads();
    }

    // partition = c + log(sum_j v_j * exp(end_j))   (v held in fp32)
    redA[bat][j] = v * __expf(__ldg(endT + j));

    // Gold-path score, 64 threads per sequence over time steps.
    float sc = 0.f;
    const int* tg = tags + (size_t)b * S_;
    const float* emB = emissions + (size_t)b * S_ * T_;
#pragma unroll 4
    for (int tt = j; tt < S_; tt += T_) {
        int tg0 = tg[tt];
        sc += __ldg(emB + (size_t)tt * T_ + tg0);
        if (tt + 1 < S_) {
            int tg1 = tg[tt + 1];
            sc += __ldg(trans + tg0 * T_ + tg1);
        }
    }
    if (j == 0) {
        sc += __ldg(startT + tg[0]);
        sc += __ldg(endT + tg[S_ - 1]);
    }
    redB[bat][j] = sc;
    __syncthreads();

    if (j == 0) {
        float sumw = 0.f;
        float sums = 0.f;
#pragma unroll
        for (int i = 0; i < T_; ++i) {
            sumw += redA[bat][i];
            sums += redB[bat][i];
        }
        double partition = c + (double)__logf(sumw);
        g_diff[b] = (float)(partition - (double)sums);
    }
}

__global__ void crf_reduce_kernel(float* __restrict__ out)
{
    __shared__ float sh[B_];
    int t = threadIdx.x;
    sh[t] = g_diff[t];
    __syncthreads();
#pragma unroll
    for (int off = B_ / 2; off > 0; off >>= 1) {
        if (t < off) sh[t] += sh[t + off];
        __syncthreads();
    }
    if (t == 0) out[0] = sh[0] / (float)B_;
}

extern "C" void kernel_launch(void* const* d_in, const int* in_sizes, int n_in,
                              void* d_out, int out_size)
{
    const float* emissions = (const float*)d_in[0];
    const int*   tags      = (const int*)d_in[1];
    const float* trans     = (const float*)d_in[2];
    const float* startT    = (const float*)d_in[3];
    const float* endT      = (const float*)d_in[4];
    float* out = (float*)d_out;

    // 5 launches per call so ncu's "-s 5 -c 1" lands on crf_forward_kernel
    // (launch index 5 = first launch of the second call).
    crf_forward_kernel<<<B_ / 2, 128>>>(emissions, tags, trans, startT, endT);
    crf_noop_kernel<<<1, 32>>>();
    crf_noop_kernel<<<1, 32>>>();
    crf_noop_kernel<<<1, 32>>>();
    crf_reduce_kernel<<<1, B_>>>(out);
}